// round 5
// baseline (speedup 1.0000x reference)
#include <cuda_runtime.h>
#include <cuda_bf16.h>
#include <math.h>
#include <stdint.h>

#define M_DIM 8192
#define H_DIM 4096
#define I_DIM 11008

// Pre-converted operands (bf16 hi/lo split), filled every call.
__device__ unsigned short g_xh[(size_t)M_DIM * H_DIM];
__device__ unsigned short g_xl[(size_t)M_DIM * H_DIM];
__device__ unsigned short g_wgh[(size_t)I_DIM * H_DIM];   // wg^T [N=I, K=H]
__device__ unsigned short g_wgl[(size_t)I_DIM * H_DIM];
__device__ unsigned short g_wuh[(size_t)I_DIM * H_DIM];
__device__ unsigned short g_wul[(size_t)I_DIM * H_DIM];
__device__ unsigned short g_wdh[(size_t)H_DIM * I_DIM];   // wd^T [N=H, K=I]
__device__ unsigned short g_wdl[(size_t)H_DIM * I_DIM];
// Intermediate h = silu(x@wg)*(x@wu), pre-split
__device__ unsigned short g_hh[(size_t)M_DIM * I_DIM];
__device__ unsigned short g_hl[(size_t)M_DIM * I_DIM];

__device__ __forceinline__ uint32_t smem_u32(const void* p) {
    uint32_t a;
    asm("{ .reg .u64 t; cvta.to.shared.u64 t, %1; cvt.u32.u64 %0, t; }" : "=r"(a) : "l"(p));
    return a;
}
__device__ __forceinline__ uint32_t pack_bf2(float a, float b) {
    uint32_t r;
    asm("cvt.rn.bf16x2.f32 %0, %1, %2;" : "=r"(r) : "f"(b), "f"(a));
    return r;
}
__device__ __forceinline__ void split2(float a, float b, uint32_t& hi, uint32_t& lo) {
    hi = pack_bf2(a, b);
    lo = pack_bf2(a - __uint_as_float(hi << 16), b - __uint_as_float(hi & 0xFFFF0000u));
}
__device__ __forceinline__ void ldsm4(uint32_t* r, uint32_t addr) {
    asm volatile("ldmatrix.sync.aligned.m8n8.x4.shared.b16 {%0,%1,%2,%3}, [%4];"
                 : "=r"(r[0]), "=r"(r[1]), "=r"(r[2]), "=r"(r[3]) : "r"(addr));
}
__device__ __forceinline__ void mma16816(float* c, const uint32_t* a, uint32_t b0, uint32_t b1) {
    asm volatile(
        "mma.sync.aligned.m16n8k16.row.col.f32.bf16.bf16.f32 "
        "{%0,%1,%2,%3}, {%4,%5,%6,%7}, {%8,%9}, {%0,%1,%2,%3};"
        : "+f"(c[0]), "+f"(c[1]), "+f"(c[2]), "+f"(c[3])
        : "r"(a[0]), "r"(a[1]), "r"(a[2]), "r"(a[3]), "r"(b0), "r"(b1));
}
__device__ __forceinline__ void cpa(uint32_t dst, const void* src) {
    asm volatile("cp.async.cg.shared.global [%0], [%1], 16;" :: "r"(dst), "l"(src));
}
#define CP_COMMIT() asm volatile("cp.async.commit_group;" ::: "memory")
#define CP_WAIT(n)  asm volatile("cp.async.wait_group %0;" :: "n"(n) : "memory")

// smem: rows stride 80B (conflict-free for ldmatrix 16B fetches, 16B-aligned).
// Stage (both GEMMs) = 40960B. 4 stages.
#define STAGE 40960
#define NSTG 4
#define SMEM_BYTES (NSTG * STAGE)

// ---------------------------------------------------------------------------
// Convert kernels
// ---------------------------------------------------------------------------
__global__ __launch_bounds__(256)
void k_cvt_x(const float* __restrict__ x)
{
    long long i = (long long)blockIdx.x * 256 + threadIdx.x;   // float4 index
    float4 v = ((const float4*)x)[i];
    uint32_t h0, l0, h1, l1;
    split2(v.x, v.y, h0, l0);
    split2(v.z, v.w, h1, l1);
    *(uint2*)&g_xh[i * 4] = make_uint2(h0, h1);
    *(uint2*)&g_xl[i * 4] = make_uint2(l0, l1);
}

// Transpose + split: src [K, N] fp32 -> dh/dl [N, K] bf16. Tile 64k x 32n.
__global__ __launch_bounds__(256)
void k_cvt_w(const float* __restrict__ src,
             unsigned short* __restrict__ dh,
             unsigned short* __restrict__ dl,
             int K, int N)
{
    __shared__ float ts[64][33];
    const int t = threadIdx.x;
    const int k0 = blockIdx.x * 64, n0 = blockIdx.y * 32;
#pragma unroll
    for (int j = 0; j < 8; j++) {
        int idx = j * 256 + t, kk = idx >> 5, nn = idx & 31;
        ts[kk][nn] = src[(long long)(k0 + kk) * N + n0 + nn];
    }
    __syncthreads();
    const int nn = t >> 3, kc = (t & 7) * 8;
    uint32_t hv[4], lv[4];
#pragma unroll
    for (int q = 0; q < 4; q++)
        split2(ts[kc + q * 2][nn], ts[kc + q * 2 + 1][nn], hv[q], lv[q]);
    long long off = (long long)(n0 + nn) * K + k0 + kc;
    *(uint4*)&dh[off] = make_uint4(hv[0], hv[1], hv[2], hv[3]);
    *(uint4*)&dl[off] = make_uint4(lv[0], lv[1], lv[2], lv[3]);
}

// ---------------------------------------------------------------------------
// GEMM1: h = silu(x@wg) * (x@wu). CTA 128m x 64n(each), BK=32, 256 thr,
// warps 4m x 2n, warp tile 32x32 per matrix. cp.async 4-stage.
// Stage layout: A_hi 0 (128r x 80B), A_lo 10240, G_hi 20480 (64r), G_lo 25600,
//               U_hi 30720, U_lo 35840.
// ---------------------------------------------------------------------------
__global__ __launch_bounds__(256, 1)
void k_gateup()
{
    extern __shared__ char smp[];
    const uint32_t sbase = smem_u32(smp);

    const int t = threadIdx.x, lane = t & 31, wid = t >> 5;
    const int wm = wid & 3, wn = wid >> 2;

    const int num_pid_m = M_DIM / 128, num_pid_n = I_DIM / 64, GROUP = 16;
    int pid = blockIdx.x;
    int gsz = GROUP * num_pid_n;
    int gid = pid / gsz;
    int first = gid * GROUP;
    int gm = min(GROUP, num_pid_m - first);
    int pid_m = first + (pid % gm);
    int pid_n = (pid % gsz) / gm;
    const int m0 = pid_m * 128, n0 = pid_n * 64;

    float accg[2][4][4], accu[2][4][4];
#pragma unroll
    for (int i = 0; i < 2; i++)
#pragma unroll
        for (int j = 0; j < 4; j++)
#pragma unroll
            for (int k = 0; k < 4; k++) { accg[i][j][k] = 0.f; accu[i][j][k] = 0.f; }

    const int KT = H_DIM / 32;   // 128

    auto issue = [&](int kt, int st) {
        const uint32_t sA = sbase + (uint32_t)st * STAGE;
        const long long kb = (long long)kt * 32;
#pragma unroll
        for (int j = 0; j < 4; j++) {
            int c = j * 256 + t, arr = c >> 9, rem = c & 511, row = rem >> 2, c4 = rem & 3;
            const unsigned short* s = (arr ? g_xl : g_xh) + (long long)(m0 + row) * H_DIM + kb + c4 * 8;
            cpa(sA + arr * 10240 + row * 80 + c4 * 16, s);
        }
#pragma unroll
        for (int j = 0; j < 4; j++) {
            int c = j * 256 + t, mat = c >> 9, rem = c & 511;
            int arr = rem >> 8, r2 = rem & 255, row = r2 >> 2, c4 = r2 & 3;
            const unsigned short* W = mat ? (arr ? g_wul : g_wuh) : (arr ? g_wgl : g_wgh);
            const unsigned short* s = W + (long long)(n0 + row) * H_DIM + kb + c4 * 8;
            cpa(sA + 20480 + mat * 10240 + arr * 5120 + row * 80 + c4 * 16, s);
        }
    };

    const uint32_t a_row  = (uint32_t)(lane & 15);
    const uint32_t a_koff = (uint32_t)((lane >> 4) * 8);
    const uint32_t b_n    = (uint32_t)((lane & 7) + ((lane >> 4) << 3));
    const uint32_t b_koff = (uint32_t)(((lane >> 3) & 1) * 8);

#pragma unroll
    for (int s = 0; s < NSTG - 1; s++) { issue(s, s); CP_COMMIT(); }

    for (int kt = 0; kt < KT; ++kt) {
        const int st = kt & (NSTG - 1);
        CP_WAIT(NSTG - 2);
        __syncthreads();
        if (kt + NSTG - 1 < KT) issue(kt + NSTG - 1, (kt + NSTG - 1) & (NSTG - 1));
        CP_COMMIT();

        const uint32_t sA = sbase + (uint32_t)st * STAGE;
#pragma unroll
        for (int ks = 0; ks < 2; ks++) {
            uint32_t ah[2][4], al[2][4];
#pragma unroll
            for (int mt = 0; mt < 2; mt++) {
                uint32_t addr = sA + (uint32_t)((wm * 32 + mt * 16 + a_row) * 80) + (uint32_t)(ks * 32) + a_koff * 2;
                ldsm4(ah[mt], addr);
                ldsm4(al[mt], addr + 10240);
            }
            {   // gate
                uint32_t bh[2][4], bl[2][4];
#pragma unroll
                for (int blk = 0; blk < 2; blk++) {
                    uint32_t addr = sA + 20480u + (uint32_t)((wn * 32 + blk * 16 + b_n) * 80) + (uint32_t)(ks * 32) + b_koff * 2;
                    ldsm4(bh[blk], addr);
                    ldsm4(bl[blk], addr + 5120);
                }
#pragma unroll
                for (int mt = 0; mt < 2; mt++)
#pragma unroll
                    for (int n8 = 0; n8 < 4; n8++) {
                        int blk = n8 >> 1, h = (n8 & 1) * 2;
                        mma16816(accg[mt][n8], ah[mt], bh[blk][h], bh[blk][h + 1]);
                        mma16816(accg[mt][n8], ah[mt], bl[blk][h], bl[blk][h + 1]);
                        mma16816(accg[mt][n8], al[mt], bh[blk][h], bh[blk][h + 1]);
                    }
            }
            {   // up
                uint32_t bh[2][4], bl[2][4];
#pragma unroll
                for (int blk = 0; blk < 2; blk++) {
                    uint32_t addr = sA + 30720u + (uint32_t)((wn * 32 + blk * 16 + b_n) * 80) + (uint32_t)(ks * 32) + b_koff * 2;
                    ldsm4(bh[blk], addr);
                    ldsm4(bl[blk], addr + 5120);
                }
#pragma unroll
                for (int mt = 0; mt < 2; mt++)
#pragma unroll
                    for (int n8 = 0; n8 < 4; n8++) {
                        int blk = n8 >> 1, h = (n8 & 1) * 2;
                        mma16816(accu[mt][n8], ah[mt], bh[blk][h], bh[blk][h + 1]);
                        mma16816(accu[mt][n8], ah[mt], bl[blk][h], bl[blk][h + 1]);
                        mma16816(accu[mt][n8], al[mt], bh[blk][h], bh[blk][h + 1]);
                    }
            }
        }
        __syncthreads();
    }

    // epilogue: h = silu(g)*u, pre-split store
#pragma unroll
    for (int mt = 0; mt < 2; mt++) {
#pragma unroll
        for (int n8 = 0; n8 < 4; n8++) {
            int row = m0 + wm * 32 + mt * 16 + (lane >> 2);
            int col = n0 + wn * 32 + n8 * 8 + (lane & 3) * 2;
#pragma unroll
            for (int half = 0; half < 2; half++) {
                int r = row + half * 8;
                float g0 = accg[mt][n8][half * 2],     u0 = accu[mt][n8][half * 2];
                float g1 = accg[mt][n8][half * 2 + 1], u1 = accu[mt][n8][half * 2 + 1];
                float h0 = g0 / (1.f + __expf(-g0)) * u0;
                float h1 = g1 / (1.f + __expf(-g1)) * u1;
                uint32_t hi, lo;
                split2(h0, h1, hi, lo);
                long long idx = (long long)r * I_DIM + col;
                *(uint32_t*)&g_hh[idx] = hi;
                *(uint32_t*)&g_hl[idx] = lo;
            }
        }
    }
}

// ---------------------------------------------------------------------------
// GEMM2: y = h @ wd. CTA 128 x 128, BK=32, warp tile 32x64. cp.async 4-stage.
// Stage: A_hi 0, A_lo 10240, B_hi 20480, B_lo 30720 (128 rows x 80B each).
// ---------------------------------------------------------------------------
__global__ __launch_bounds__(256, 1)
void k_down(float* __restrict__ y)
{
    extern __shared__ char smp[];
    const uint32_t sbase = smem_u32(smp);

    const int t = threadIdx.x, lane = t & 31, wid = t >> 5;
    const int wm = wid & 3, wn = wid >> 2;

    const int num_pid_m = M_DIM / 128, num_pid_n = H_DIM / 128, GROUP = 8;
    int pid = blockIdx.x;
    int gsz = GROUP * num_pid_n;
    int gid = pid / gsz;
    int first = gid * GROUP;
    int gm = min(GROUP, num_pid_m - first);
    int pid_m = first + (pid % gm);
    int pid_n = (pid % gsz) / gm;
    const int m0 = pid_m * 128, n0 = pid_n * 128;

    float acc[2][8][4];
#pragma unroll
    for (int i = 0; i < 2; i++)
#pragma unroll
        for (int j = 0; j < 8; j++)
#pragma unroll
            for (int k = 0; k < 4; k++) acc[i][j][k] = 0.f;

    const int KT = I_DIM / 32;   // 344

    auto issue = [&](int kt, int st) {
        const uint32_t sA = sbase + (uint32_t)st * STAGE;
        const long long kb = (long long)kt * 32;
#pragma unroll
        for (int j = 0; j < 4; j++) {
            int c = j * 256 + t, arr = c >> 9, rem = c & 511, row = rem >> 2, c4 = rem & 3;
            const unsigned short* s = (arr ? g_hl : g_hh) + (long long)(m0 + row) * I_DIM + kb + c4 * 8;
            cpa(sA + arr * 10240 + row * 80 + c4 * 16, s);
        }
#pragma unroll
        for (int j = 0; j < 4; j++) {
            int c = j * 256 + t, arr = c >> 9, rem = c & 511, row = rem >> 2, c4 = rem & 3;
            const unsigned short* s = (arr ? g_wdl : g_wdh) + (long long)(n0 + row) * I_DIM + kb + c4 * 8;
            cpa(sA + 20480 + arr * 10240 + row * 80 + c4 * 16, s);
        }
    };

    const uint32_t a_row  = (uint32_t)(lane & 15);
    const uint32_t a_koff = (uint32_t)((lane >> 4) * 8);
    const uint32_t b_n    = (uint32_t)((lane & 7) + ((lane >> 4) << 3));
    const uint32_t b_koff = (uint32_t)(((lane >> 3) & 1) * 8);

#pragma unroll
    for (int s = 0; s < NSTG - 1; s++) { issue(s, s); CP_COMMIT(); }

    for (int kt = 0; kt < KT; ++kt) {
        const int st = kt & (NSTG - 1);
        CP_WAIT(NSTG - 2);
        __syncthreads();
        if (kt + NSTG - 1 < KT) issue(kt + NSTG - 1, (kt + NSTG - 1) & (NSTG - 1));
        CP_COMMIT();

        const uint32_t sA = sbase + (uint32_t)st * STAGE;
#pragma unroll
        for (int ks = 0; ks < 2; ks++) {
            uint32_t ah[2][4], al[2][4];
#pragma unroll
            for (int mt = 0; mt < 2; mt++) {
                uint32_t addr = sA + (uint32_t)((wm * 32 + mt * 16 + a_row) * 80) + (uint32_t)(ks * 32) + a_koff * 2;
                ldsm4(ah[mt], addr);
                ldsm4(al[mt], addr + 10240);
            }
#pragma unroll
            for (int half = 0; half < 2; half++) {
                uint32_t bh[2][4], bl[2][4];
#pragma unroll
                for (int b = 0; b < 2; b++) {
                    int blk = half * 2 + b;
                    uint32_t addr = sA + 20480u + (uint32_t)((wn * 64 + blk * 16 + b_n) * 80) + (uint32_t)(ks * 32) + b_koff * 2;
                    ldsm4(bh[b], addr);
                    ldsm4(bl[b], addr + 10240);
                }
#pragma unroll
                for (int mt = 0; mt < 2; mt++)
#pragma unroll
                    for (int q = 0; q < 4; q++) {
                        int n8 = half * 4 + q;
                        int b = q >> 1, h = (q & 1) * 2;
                        mma16816(acc[mt][n8], ah[mt], bh[b][h], bh[b][h + 1]);
                        mma16816(acc[mt][n8], ah[mt], bl[b][h], bl[b][h + 1]);
                        mma16816(acc[mt][n8], al[mt], bh[b][h], bh[b][h + 1]);
                    }
            }
        }
        __syncthreads();
    }

#pragma unroll
    for (int mt = 0; mt < 2; mt++) {
#pragma unroll
        for (int n8 = 0; n8 < 8; n8++) {
            int row = m0 + wm * 32 + mt * 16 + (lane >> 2);
            int col = n0 + wn * 64 + n8 * 8 + (lane & 3) * 2;
#pragma unroll
            for (int half = 0; half < 2; half++) {
                int r = row + half * 8;
                float2 o = make_float2(acc[mt][n8][half * 2], acc[mt][n8][half * 2 + 1]);
                *(float2*)(y + (long long)r * H_DIM + col) = o;
            }
        }
    }
}

// ---------------------------------------------------------------------------
extern "C" void kernel_launch(void* const* d_in, const int* in_sizes, int n_in,
                              void* d_out, int out_size)
{
    const float* x  = (const float*)d_in[0];
    const float* wg = (const float*)d_in[1];
    const float* wu = (const float*)d_in[2];
    const float* wd = (const float*)d_in[3];
    float* y = (float*)d_out;

    cudaFuncSetAttribute(k_gateup, cudaFuncAttributeMaxDynamicSharedMemorySize, SMEM_BYTES);
    cudaFuncSetAttribute(k_down,   cudaFuncAttributeMaxDynamicSharedMemorySize, SMEM_BYTES);

    unsigned short *wgh, *wgl, *wuh, *wul, *wdh, *wdl;
    cudaGetSymbolAddress((void**)&wgh, g_wgh);
    cudaGetSymbolAddress((void**)&wgl, g_wgl);
    cudaGetSymbolAddress((void**)&wuh, g_wuh);
    cudaGetSymbolAddress((void**)&wul, g_wul);
    cudaGetSymbolAddress((void**)&wdh, g_wdh);
    cudaGetSymbolAddress((void**)&wdl, g_wdl);

    // converts
    k_cvt_x<<<(M_DIM * H_DIM / 4) / 256, 256>>>(x);
    k_cvt_w<<<dim3(H_DIM / 64, I_DIM / 32), 256>>>(wg, wgh, wgl, H_DIM, I_DIM);
    k_cvt_w<<<dim3(H_DIM / 64, I_DIM / 32), 256>>>(wu, wuh, wul, H_DIM, I_DIM);
    k_cvt_w<<<dim3(I_DIM / 64, H_DIM / 32), 256>>>(wd, wdh, wdl, I_DIM, H_DIM);

    const int grid1 = (M_DIM / 128) * (I_DIM / 64);    // 11008
    const int grid2 = (M_DIM / 128) * (H_DIM / 128);   // 2048
    k_gateup<<<grid1, 256, SMEM_BYTES>>>();
    k_down<<<grid2, 256, SMEM_BYTES>>>(y);
}

// round 7
// speedup vs baseline: 1.5303x; 1.5303x over previous
#include <cuda_runtime.h>
#include <math.h>
#include <stdint.h>

#define M_DIM 8192
#define H_DIM 4096
#define I_DIM 11008

// tf32-rounded operands (fp32 bit patterns, low 13 mantissa bits zero)
__device__ float g_x [(size_t)M_DIM * H_DIM];
__device__ float g_wg[(size_t)I_DIM * H_DIM];   // wg^T [N=I, K=H]
__device__ float g_wu[(size_t)I_DIM * H_DIM];   // wu^T
__device__ float g_wd[(size_t)H_DIM * I_DIM];   // wd^T [N=H, K=I]
__device__ float g_h [(size_t)M_DIM * I_DIM];   // silu(x@wg)*(x@wu), tf32-rounded

__device__ __forceinline__ uint32_t smem_u32(const void* p) {
    uint32_t a;
    asm("{ .reg .u64 t; cvta.to.shared.u64 t, %1; cvt.u32.u64 %0, t; }" : "=r"(a) : "l"(p));
    return a;
}
__device__ __forceinline__ float tf32r(float f) {
    uint32_t r;
    asm("cvt.rna.tf32.f32 %0, %1;" : "=r"(r) : "f"(f));
    return __uint_as_float(r);
}
__device__ __forceinline__ void mma_tf32(float* c, float a0, float a1, float a2, float a3,
                                         float b0, float b1) {
    asm volatile(
        "mma.sync.aligned.m16n8k8.row.col.f32.tf32.tf32.f32 "
        "{%0,%1,%2,%3}, {%4,%5,%6,%7}, {%8,%9}, {%0,%1,%2,%3};"
        : "+f"(c[0]), "+f"(c[1]), "+f"(c[2]), "+f"(c[3])
        : "r"(__float_as_uint(a0)), "r"(__float_as_uint(a1)),
          "r"(__float_as_uint(a2)), "r"(__float_as_uint(a3)),
          "r"(__float_as_uint(b0)), "r"(__float_as_uint(b1)));
}
__device__ __forceinline__ void cpa(uint32_t dst, const void* src) {
    asm volatile("cp.async.cg.shared.global [%0], [%1], 16;" :: "r"(dst), "l"(src));
}
#define CP_COMMIT() asm volatile("cp.async.commit_group;" ::: "memory")
#define CP_WAIT(n)  asm volatile("cp.async.wait_group %0;" :: "n"(n) : "memory")

// smem: fp32 tiles, row = 32 k-floats padded to 36 (144B). Conflict-free frag LDS.
#define SROW 36
#define TILE_BYTES (128 * SROW * 4)     // 18432
#define STAGE (2 * TILE_BYTES)          // 36864 (A + B)
#define NSTG 3
#define SMEM_BYTES (NSTG * STAGE)       // 110592

// ---------------------------------------------------------------------------
// Convert kernels (once per call)
// ---------------------------------------------------------------------------
__global__ __launch_bounds__(256)
void k_cvt_x(const float* __restrict__ x)
{
    long long i = (long long)blockIdx.x * 256 + threadIdx.x;
    float4 v = ((const float4*)x)[i];
    v.x = tf32r(v.x); v.y = tf32r(v.y); v.z = tf32r(v.z); v.w = tf32r(v.w);
    ((float4*)g_x)[i] = v;
}

// transpose+round: src [K, N] -> dst [N, K]; tile 64k x 32n
__global__ __launch_bounds__(256)
void k_cvt_w(const float* __restrict__ src, float* __restrict__ dst, int K, int N)
{
    __shared__ float ts[64][33];
    const int t = threadIdx.x;
    const int k0 = blockIdx.x * 64, n0 = blockIdx.y * 32;
#pragma unroll
    for (int j = 0; j < 8; j++) {
        int idx = j * 256 + t, kk = idx >> 5, nn = idx & 31;
        ts[kk][nn] = src[(long long)(k0 + kk) * N + n0 + nn];
    }
    __syncthreads();
    const int nn = t >> 3, kc = (t & 7) * 8;
    float4 o0, o1;
    o0.x = tf32r(ts[kc + 0][nn]); o0.y = tf32r(ts[kc + 1][nn]);
    o0.z = tf32r(ts[kc + 2][nn]); o0.w = tf32r(ts[kc + 3][nn]);
    o1.x = tf32r(ts[kc + 4][nn]); o1.y = tf32r(ts[kc + 5][nn]);
    o1.z = tf32r(ts[kc + 6][nn]); o1.w = tf32r(ts[kc + 7][nn]);
    long long off = (long long)(n0 + nn) * K + k0 + kc;
    *(float4*)&dst[off]     = o0;
    *(float4*)&dst[off + 4] = o1;
}

// ---------------------------------------------------------------------------
// GEMM1: h = silu(x@wg) * (x@wu). CTA computes 128m x 64n of BOTH gate & up.
// B smem tile: rows 0-63 = wg[n0..n0+63], rows 64-127 = wu[n0..n0+63]. BK=32.
// 256 thr, warps 4m x 2n; warp tile 32m x 32n per matrix.
// ---------------------------------------------------------------------------
__global__ __launch_bounds__(256, 2)
void k_gateup()
{
    extern __shared__ char smp[];

    const int t = threadIdx.x, lane = t & 31, wid = t >> 5;
    const int wm = wid & 3, wn = wid >> 2;

    const int num_pid_m = M_DIM / 128, num_pid_n = I_DIM / 64, GROUP = 16;
    int pid = blockIdx.x;
    int gsz = GROUP * num_pid_n;
    int gid = pid / gsz;
    int first = gid * GROUP;
    int gm = min(GROUP, num_pid_m - first);
    int pid_m = first + (pid % gm);
    int pid_n = (pid % gsz) / gm;
    const int m0 = pid_m * 128, n0 = pid_n * 64;

    float acc[2][8][4];   // n8 0-3 gate, 4-7 up
#pragma unroll
    for (int i = 0; i < 2; i++)
#pragma unroll
        for (int j = 0; j < 8; j++)
#pragma unroll
            for (int k = 0; k < 4; k++) acc[i][j][k] = 0.f;

    const int KT = H_DIM / 32;   // 128

    const uint32_t sbase = smem_u32(smp);
    auto issue = [&](int kt, int st) {
        const uint32_t sA = sbase + (uint32_t)st * STAGE;
        const long long kb = (long long)kt * 32;
#pragma unroll
        for (int j = 0; j < 4; j++) {
            int c = j * 256 + t, row = c >> 3, c16 = c & 7;
            cpa(sA + row * 144 + c16 * 16,
                g_x + (long long)(m0 + row) * H_DIM + kb + c16 * 4);
        }
#pragma unroll
        for (int j = 0; j < 4; j++) {
            int c = j * 256 + t, row = c >> 3, c16 = c & 7;
            const float* W = (row < 64) ? g_wg : g_wu;
            cpa(sA + TILE_BYTES + row * 144 + c16 * 16,
                W + (long long)(n0 + (row & 63)) * H_DIM + kb + c16 * 4);
        }
    };

    issue(0, 0); CP_COMMIT();
    issue(1, 1); CP_COMMIT();

    const int ar = lane >> 2, ac = lane & 3;
    int sc = 0;
    for (int kt = 0; kt < KT; ++kt) {
        CP_WAIT(1);
        __syncthreads();
        if (kt + 2 < KT) {
            int sn = sc + 2; if (sn >= NSTG) sn -= NSTG;
            issue(kt + 2, sn);
        }
        CP_COMMIT();

        const char* sp = smp + sc * STAGE;
        const float* fA = (const float*)sp;
        const float* fB = (const float*)(sp + TILE_BYTES);
#pragma unroll
        for (int ks = 0; ks < 4; ks++) {
            float a[2][4];
#pragma unroll
            for (int mt = 0; mt < 2; mt++) {
                int idx = (wm * 32 + mt * 16 + ar) * SROW + ks * 8 + ac;
                a[mt][0] = fA[idx];
                a[mt][1] = fA[idx + 8 * SROW];
                a[mt][2] = fA[idx + 4];
                a[mt][3] = fA[idx + 8 * SROW + 4];
            }
#pragma unroll
            for (int n8 = 0; n8 < 8; n8++) {
                int rowb = (n8 < 4) ? (wn * 32 + n8 * 8) : (64 + wn * 32 + (n8 - 4) * 8);
                int bidx = (rowb + ar) * SROW + ks * 8 + ac;
                float b0 = fB[bidx], b1 = fB[bidx + 4];
#pragma unroll
                for (int mt = 0; mt < 2; mt++)
                    mma_tf32(acc[mt][n8], a[mt][0], a[mt][1], a[mt][2], a[mt][3], b0, b1);
            }
        }
        __syncthreads();
        sc = sc + 1; if (sc >= NSTG) sc -= NSTG;
    }

    // epilogue: h = silu(g)*u, tf32-rounded
#pragma unroll
    for (int mt = 0; mt < 2; mt++) {
#pragma unroll
        for (int p = 0; p < 4; p++) {
            int row = m0 + wm * 32 + mt * 16 + (lane >> 2);
            int col = n0 + wn * 32 + p * 8 + (lane & 3) * 2;
#pragma unroll
            for (int half = 0; half < 2; half++) {
                int r = row + half * 8;
                float g0 = acc[mt][p][half * 2],     u0 = acc[mt][p + 4][half * 2];
                float g1 = acc[mt][p][half * 2 + 1], u1 = acc[mt][p + 4][half * 2 + 1];
                float h0 = g0 / (1.f + __expf(-g0)) * u0;
                float h1 = g1 / (1.f + __expf(-g1)) * u1;
                float2 o = make_float2(tf32r(h0), tf32r(h1));
                *(float2*)&g_h[(long long)r * I_DIM + col] = o;
            }
        }
    }
}

// ---------------------------------------------------------------------------
// GEMM2: y = h @ wd. CTA 128 x 128, BK=32, warp tile 32m x 64n.
// ---------------------------------------------------------------------------
__global__ __launch_bounds__(256, 2)
void k_down(float* __restrict__ y)
{
    extern __shared__ char smp[];

    const int t = threadIdx.x, lane = t & 31, wid = t >> 5;
    const int wm = wid & 3, wn = wid >> 2;

    const int num_pid_m = M_DIM / 128, num_pid_n = H_DIM / 128, GROUP = 8;
    int pid = blockIdx.x;
    int gsz = GROUP * num_pid_n;
    int gid = pid / gsz;
    int first = gid * GROUP;
    int gm = min(GROUP, num_pid_m - first);
    int pid_m = first + (pid % gm);
    int pid_n = (pid % gsz) / gm;
    const int m0 = pid_m * 128, n0 = pid_n * 128;

    float acc[2][8][4];
#pragma unroll
    for (int i = 0; i < 2; i++)
#pragma unroll
        for (int j = 0; j < 8; j++)
#pragma unroll
            for (int k = 0; k < 4; k++) acc[i][j][k] = 0.f;

    const int KT = I_DIM / 32;   // 344

    const uint32_t sbase = smem_u32(smp);
    auto issue = [&](int kt, int st) {
        const uint32_t sA = sbase + (uint32_t)st * STAGE;
        const long long kb = (long long)kt * 32;
#pragma unroll
        for (int j = 0; j < 4; j++) {
            int c = j * 256 + t, row = c >> 3, c16 = c & 7;
            cpa(sA + row * 144 + c16 * 16,
                g_h + (long long)(m0 + row) * I_DIM + kb + c16 * 4);
        }
#pragma unroll
        for (int j = 0; j < 4; j++) {
            int c = j * 256 + t, row = c >> 3, c16 = c & 7;
            cpa(sA + TILE_BYTES + row * 144 + c16 * 16,
                g_wd + (long long)(n0 + row) * I_DIM + kb + c16 * 4);
        }
    };

    issue(0, 0); CP_COMMIT();
    issue(1, 1); CP_COMMIT();

    const int ar = lane >> 2, ac = lane & 3;
    int sc = 0;
    for (int kt = 0; kt < KT; ++kt) {
        CP_WAIT(1);
        __syncthreads();
        if (kt + 2 < KT) {
            int sn = sc + 2; if (sn >= NSTG) sn -= NSTG;
            issue(kt + 2, sn);
        }
        CP_COMMIT();

        const char* sp = smp + sc * STAGE;
        const float* fA = (const float*)sp;
        const float* fB = (const float*)(sp + TILE_BYTES);
#pragma unroll
        for (int ks = 0; ks < 4; ks++) {
            float a[2][4];
#pragma unroll
            for (int mt = 0; mt < 2; mt++) {
                int idx = (wm * 32 + mt * 16 + ar) * SROW + ks * 8 + ac;
                a[mt][0] = fA[idx];
                a[mt][1] = fA[idx + 8 * SROW];
                a[mt][2] = fA[idx + 4];
                a[mt][3] = fA[idx + 8 * SROW + 4];
            }
#pragma unroll
            for (int n8 = 0; n8 < 8; n8++) {
                int bidx = (wn * 64 + n8 * 8 + ar) * SROW + ks * 8 + ac;
                float b0 = fB[bidx], b1 = fB[bidx + 4];
#pragma unroll
                for (int mt = 0; mt < 2; mt++)
                    mma_tf32(acc[mt][n8], a[mt][0], a[mt][1], a[mt][2], a[mt][3], b0, b1);
            }
        }
        __syncthreads();
        sc = sc + 1; if (sc >= NSTG) sc -= NSTG;
    }

#pragma unroll
    for (int mt = 0; mt < 2; mt++) {
#pragma unroll
        for (int n8 = 0; n8 < 8; n8++) {
            int row = m0 + wm * 32 + mt * 16 + (lane >> 2);
            int col = n0 + wn * 64 + n8 * 8 + (lane & 3) * 2;
#pragma unroll
            for (int half = 0; half < 2; half++) {
                int r = row + half * 8;
                float2 o = make_float2(acc[mt][n8][half * 2], acc[mt][n8][half * 2 + 1]);
                *(float2*)(y + (long long)r * H_DIM + col) = o;
            }
        }
    }
}

// ---------------------------------------------------------------------------
extern "C" void kernel_launch(void* const* d_in, const int* in_sizes, int n_in,
                              void* d_out, int out_size)
{
    const float* x  = (const float*)d_in[0];
    const float* wg = (const float*)d_in[1];
    const float* wu = (const float*)d_in[2];
    const float* wd = (const float*)d_in[3];
    float* y = (float*)d_out;

    cudaFuncSetAttribute(k_gateup, cudaFuncAttributeMaxDynamicSharedMemorySize, SMEM_BYTES);
    cudaFuncSetAttribute(k_down,   cudaFuncAttributeMaxDynamicSharedMemorySize, SMEM_BYTES);

    float *wgp, *wup, *wdp;
    cudaGetSymbolAddress((void**)&wgp, g_wg);
    cudaGetSymbolAddress((void**)&wup, g_wu);
    cudaGetSymbolAddress((void**)&wdp, g_wd);

    k_cvt_x<<<(M_DIM * H_DIM / 4) / 256, 256>>>(x);
    k_cvt_w<<<dim3(H_DIM / 64, I_DIM / 32), 256>>>(wg, wgp, H_DIM, I_DIM);
    k_cvt_w<<<dim3(H_DIM / 64, I_DIM / 32), 256>>>(wu, wup, H_DIM, I_DIM);
    k_cvt_w<<<dim3(I_DIM / 64, H_DIM / 32), 256>>>(wd, wdp, I_DIM, H_DIM);

    const int grid1 = (M_DIM / 128) * (I_DIM / 64);    // 64 * 172 = 11008
    const int grid2 = (M_DIM / 128) * (H_DIM / 128);   // 64 * 32  = 2048
    k_gateup<<<grid1, 256, SMEM_BYTES>>>();
    k_down<<<grid2, 256, SMEM_BYTES>>>(y);
}

// round 8
// speedup vs baseline: 2.0645x; 1.3491x over previous
#include <cuda_runtime.h>
#include <math.h>
#include <stdint.h>

#define M_DIM 8192
#define H_DIM 4096
#define I_DIM 11008

// Fragment-packed operands (tf32-rounded fp32 bit patterns).
// A-pack: [rowTiles16][kTiles8][lane32][4]  (PTX m16n8k8 A fragment order)
// B-pack: [nTiles8][kTiles8][lane32][2]     (PTX m16n8k8 B fragment order)
__device__ float g_xp [(size_t)M_DIM * H_DIM];   // x    A-pack (K=H)
__device__ float g_wgp[(size_t)I_DIM * H_DIM];   // wg^T B-pack (N=I, K=H)
__device__ float g_wup[(size_t)I_DIM * H_DIM];   // wu^T B-pack
__device__ float g_wdp[(size_t)H_DIM * I_DIM];   // wd^T B-pack (N=H, K=I)
__device__ float g_hp [(size_t)M_DIM * I_DIM];   // h    A-pack (K=I)

__device__ __forceinline__ uint32_t smem_u32(const void* p) {
    uint32_t a;
    asm("{ .reg .u64 t; cvta.to.shared.u64 t, %1; cvt.u32.u64 %0, t; }" : "=r"(a) : "l"(p));
    return a;
}
__device__ __forceinline__ float tf32r(float f) {
    uint32_t r;
    asm("cvt.rna.tf32.f32 %0, %1;" : "=r"(r) : "f"(f));
    return __uint_as_float(r);
}
__device__ __forceinline__ void mma_tf32(float* c, float a0, float a1, float a2, float a3,
                                         float b0, float b1) {
    asm volatile(
        "mma.sync.aligned.m16n8k8.row.col.f32.tf32.tf32.f32 "
        "{%0,%1,%2,%3}, {%4,%5,%6,%7}, {%8,%9}, {%0,%1,%2,%3};"
        : "+f"(c[0]), "+f"(c[1]), "+f"(c[2]), "+f"(c[3])
        : "r"(__float_as_uint(a0)), "r"(__float_as_uint(a1)),
          "r"(__float_as_uint(a2)), "r"(__float_as_uint(a3)),
          "r"(__float_as_uint(b0)), "r"(__float_as_uint(b1)));
}
__device__ __forceinline__ void cpa(uint32_t dst, const void* src) {
    asm volatile("cp.async.cg.shared.global [%0], [%1], 16;" :: "r"(dst), "l"(src));
}
#define CP_COMMIT() asm volatile("cp.async.commit_group;" ::: "memory")
#define CP_WAIT(n)  asm volatile("cp.async.wait_group %0;" :: "n"(n) : "memory")

// stage: A 32 tiles x 512B = 16KB, B 64 tiles x 256B = 16KB
#define A_BYTES 16384
#define STAGE 32768
#define NSTG 3
#define SMEM_BYTES (NSTG * STAGE)   // 98304 -> 2 CTAs/SM

// ---------------------------------------------------------------------------
// Convert kernels (once per call; DRAM-bound, ~250us total)
// ---------------------------------------------------------------------------
// x [M,K] row-major -> A-pack
__global__ __launch_bounds__(256)
void k_cvt_xA(const float* __restrict__ x)
{
    long long g = (long long)blockIdx.x * 256 + threadIdx.x;
    long long tile = g >> 5;
    int lane = (int)(g & 31);
    const int K8 = H_DIM / 8;
    int mt = (int)(tile / K8), kt = (int)(tile % K8);
    long long r = mt * 16 + (lane >> 2);
    int k = kt * 8 + (lane & 3);
    float4 o;
    o.x = tf32r(x[r * H_DIM + k]);
    o.y = tf32r(x[(r + 8) * H_DIM + k]);
    o.z = tf32r(x[r * H_DIM + k + 4]);
    o.w = tf32r(x[(r + 8) * H_DIM + k + 4]);
    *(float4*)&g_xp[tile * 128 + lane * 4] = o;
}

// w [K,N] row-major -> w^T B-pack [N/8][K/8][lane][2]
__global__ __launch_bounds__(256)
void k_cvt_wB(const float* __restrict__ w, float* __restrict__ dst, int K, int N)
{
    long long g = (long long)blockIdx.x * 256 + threadIdx.x;
    long long tile = g >> 5;
    int lane = (int)(g & 31);
    const int K8 = K / 8;
    int nt = (int)(tile / K8), kt = (int)(tile % K8);
    long long k = kt * 8 + (lane & 3);
    int n = nt * 8 + (lane >> 2);
    float2 o;
    o.x = tf32r(w[k * N + n]);
    o.y = tf32r(w[(k + 4) * N + n]);
    *(float2*)&dst[tile * 64 + lane * 2] = o;
}

// ---------------------------------------------------------------------------
// GEMM1: h = silu(x@wg)*(x@wu). CTA 128m x 64n (gate+up), BK=32 (4 k-tiles).
// 256 thr, warps 4m x 2n; per warp: 32m x 32n gate + 32n up.
// B smem tiles: gate (nt 0-7) then up (nt 0-7), each x 4 ktiles.
// ---------------------------------------------------------------------------
__global__ __launch_bounds__(256, 2)
void k_gateup()
{
    extern __shared__ char smp[];
    const uint32_t sbase = smem_u32(smp);

    const int t = threadIdx.x, lane = t & 31, wid = t >> 5;
    const int wm = wid & 3, wn = wid >> 2;

    const int num_pid_m = M_DIM / 128, num_pid_n = I_DIM / 64, GROUP = 16;
    int pid = blockIdx.x;
    int gsz = GROUP * num_pid_n;
    int gid = pid / gsz;
    int first = gid * GROUP;
    int gm = min(GROUP, num_pid_m - first);
    int pid_m = first + (pid % gm);
    int pid_n = (pid % gsz) / gm;
    const int m0 = pid_m * 128, n0 = pid_n * 64;

    const int K8 = H_DIM / 8;
    const int mtile0 = m0 >> 4, ntile0 = n0 >> 3;

    float acc[2][8][4];   // n8 0-3 gate, 4-7 up
#pragma unroll
    for (int i = 0; i < 2; i++)
#pragma unroll
        for (int j = 0; j < 8; j++)
#pragma unroll
            for (int k = 0; k < 4; k++) acc[i][j][k] = 0.f;

    const int KT = H_DIM / 32;   // 128

    auto issue = [&](int kt, int st) {
        const uint32_t sA = sbase + (uint32_t)st * STAGE;
        const int ktb = kt * 4;
        // A: 1024 x 16B chunks, 4/thread
#pragma unroll
        for (int j = 0; j < 4; j++) {
            int c = j * 256 + t;
            int tile = c >> 5, ln = c & 31;
            int mtl = tile >> 2, ktl = tile & 3;
            cpa(sA + tile * 512 + ln * 16,
                g_xp + ((long long)(mtile0 + mtl) * K8 + ktb + ktl) * 128 + ln * 4);
        }
        // B: 1024 x 16B chunks (gate 0-511, up 512-1023), 4/thread
#pragma unroll
        for (int j = 0; j < 4; j++) {
            int c = j * 256 + t;
            int tile = c >> 4, pr = c & 15;
            int mat = tile >> 5, ntl = (tile >> 2) & 7, ktl = tile & 3;
            const float* W = mat ? g_wup : g_wgp;
            cpa(sA + A_BYTES + tile * 256 + pr * 16,
                W + ((long long)(ntile0 + ntl) * K8 + ktb + ktl) * 64 + pr * 4);
        }
    };

    issue(0, 0); CP_COMMIT();
    issue(1, 1); CP_COMMIT();

    int sc = 0;
    for (int kt = 0; kt < KT; ++kt) {
        CP_WAIT(1);
        __syncthreads();
        if (kt + 2 < KT) {
            int sn = sc + 2; if (sn >= NSTG) sn -= NSTG;
            issue(kt + 2, sn);
        }
        CP_COMMIT();

        const char* sp = smp + sc * STAGE;
#pragma unroll
        for (int ks = 0; ks < 4; ks++) {
            float4 a[2];
#pragma unroll
            for (int mt = 0; mt < 2; mt++)
                a[mt] = *(const float4*)(sp + ((wm * 2 + mt) * 4 + ks) * 512 + lane * 16);
#pragma unroll
            for (int n8 = 0; n8 < 8; n8++) {
                int mat = n8 >> 2;
                int tile = (mat * 8 + wn * 4 + (n8 & 3)) * 4 + ks;
                float2 b = *(const float2*)(sp + A_BYTES + tile * 256 + lane * 8);
#pragma unroll
                for (int mt = 0; mt < 2; mt++)
                    mma_tf32(acc[mt][n8], a[mt].x, a[mt].y, a[mt].z, a[mt].w, b.x, b.y);
            }
        }
        __syncthreads();
        sc = sc + 1; if (sc >= NSTG) sc -= NSTG;
    }

    // Epilogue: h = silu(g)*u, then repack to A-pack layout via smem staging.
    // Per-warp 4KB staging buffer (pipeline smem is idle now).
    {
        char* buf = smp + wid * 4096;
        const int r0 = lane >> 2, c0 = (lane & 3) * 2;
#pragma unroll
        for (int mt = 0; mt < 2; mt++) {
#pragma unroll
            for (int p = 0; p < 4; p++) {
                int q = mt * 4 + p;
                float g0 = acc[mt][p][0], u0 = acc[mt][p + 4][0];
                float g1 = acc[mt][p][1], u1 = acc[mt][p + 4][1];
                float g2 = acc[mt][p][2], u2 = acc[mt][p + 4][2];
                float g3 = acc[mt][p][3], u3 = acc[mt][p + 4][3];
                float h0 = g0 / (1.f + __expf(-g0)) * u0;
                float h1 = g1 / (1.f + __expf(-g1)) * u1;
                float h2 = g2 / (1.f + __expf(-g2)) * u2;
                float h3 = g3 / (1.f + __expf(-g3)) * u3;
                *(float2*)(buf + q * 512 + (r0 * 8 + c0) * 4)       = make_float2(h0, h1);
                *(float2*)(buf + q * 512 + ((r0 + 8) * 8 + c0) * 4) = make_float2(h2, h3);
            }
        }
        __syncwarp();
        const int I8 = I_DIM / 8;
        const int lr = lane >> 2, lk = lane & 3;
#pragma unroll
        for (int mt = 0; mt < 2; mt++) {
#pragma unroll
            for (int p = 0; p < 4; p++) {
                int q = mt * 4 + p;
                const float* tb = (const float*)(buf + q * 512);
                float4 o;
                o.x = tf32r(tb[lr * 8 + lk]);
                o.y = tf32r(tb[(lr + 8) * 8 + lk]);
                o.z = tf32r(tb[lr * 8 + lk + 4]);
                o.w = tf32r(tb[(lr + 8) * 8 + lk + 4]);
                long long Mt = (m0 + wm * 32 + mt * 16) >> 4;
                long long Kt = (n0 + wn * 32 + p * 8) >> 3;
                *(float4*)&g_hp[(Mt * I8 + Kt) * 128 + lane * 4] = o;
            }
        }
    }
}

// ---------------------------------------------------------------------------
// GEMM2: y = h @ wd. CTA 128m x 128n, BK=32, warp tile 32m x 64n.
// ---------------------------------------------------------------------------
__global__ __launch_bounds__(256, 2)
void k_down(float* __restrict__ y)
{
    extern __shared__ char smp[];
    const uint32_t sbase = smem_u32(smp);

    const int t = threadIdx.x, lane = t & 31, wid = t >> 5;
    const int wm = wid & 3, wn = wid >> 2;

    const int num_pid_m = M_DIM / 128, num_pid_n = H_DIM / 128, GROUP = 8;
    int pid = blockIdx.x;
    int gsz = GROUP * num_pid_n;
    int gid = pid / gsz;
    int first = gid * GROUP;
    int gm = min(GROUP, num_pid_m - first);
    int pid_m = first + (pid % gm);
    int pid_n = (pid % gsz) / gm;
    const int m0 = pid_m * 128, n0 = pid_n * 128;

    const int K8 = I_DIM / 8;
    const int mtile0 = m0 >> 4, ntile0 = n0 >> 3;

    float acc[2][8][4];
#pragma unroll
    for (int i = 0; i < 2; i++)
#pragma unroll
        for (int j = 0; j < 8; j++)
#pragma unroll
            for (int k = 0; k < 4; k++) acc[i][j][k] = 0.f;

    const int KT = I_DIM / 32;   // 344

    auto issue = [&](int kt, int st) {
        const uint32_t sA = sbase + (uint32_t)st * STAGE;
        const int ktb = kt * 4;
#pragma unroll
        for (int j = 0; j < 4; j++) {
            int c = j * 256 + t;
            int tile = c >> 5, ln = c & 31;
            int mtl = tile >> 2, ktl = tile & 3;
            cpa(sA + tile * 512 + ln * 16,
                g_hp + ((long long)(mtile0 + mtl) * K8 + ktb + ktl) * 128 + ln * 4);
        }
#pragma unroll
        for (int j = 0; j < 4; j++) {
            int c = j * 256 + t;
            int tile = c >> 4, pr = c & 15;
            int ntl = tile >> 2, ktl = tile & 3;   // 16 n-tiles x 4 k-tiles
            cpa(sA + A_BYTES + tile * 256 + pr * 16,
                g_wdp + ((long long)(ntile0 + ntl) * K8 + ktb + ktl) * 64 + pr * 4);
        }
    };

    issue(0, 0); CP_COMMIT();
    issue(1, 1); CP_COMMIT();

    int sc = 0;
    for (int kt = 0; kt < KT; ++kt) {
        CP_WAIT(1);
        __syncthreads();
        if (kt + 2 < KT) {
            int sn = sc + 2; if (sn >= NSTG) sn -= NSTG;
            issue(kt + 2, sn);
        }
        CP_COMMIT();

        const char* sp = smp + sc * STAGE;
#pragma unroll
        for (int ks = 0; ks < 4; ks++) {
            float4 a[2];
#pragma unroll
            for (int mt = 0; mt < 2; mt++)
                a[mt] = *(const float4*)(sp + ((wm * 2 + mt) * 4 + ks) * 512 + lane * 16);
#pragma unroll
            for (int n8 = 0; n8 < 8; n8++) {
                int tile = (wn * 8 + n8) * 4 + ks;
                float2 b = *(const float2*)(sp + A_BYTES + tile * 256 + lane * 8);
#pragma unroll
                for (int mt = 0; mt < 2; mt++)
                    mma_tf32(acc[mt][n8], a[mt].x, a[mt].y, a[mt].z, a[mt].w, b.x, b.y);
            }
        }
        __syncthreads();
        sc = sc + 1; if (sc >= NSTG) sc -= NSTG;
    }

#pragma unroll
    for (int mt = 0; mt < 2; mt++) {
#pragma unroll
        for (int n8 = 0; n8 < 8; n8++) {
            int row = m0 + wm * 32 + mt * 16 + (lane >> 2);
            int col = n0 + wn * 64 + n8 * 8 + (lane & 3) * 2;
#pragma unroll
            for (int half = 0; half < 2; half++) {
                int r = row + half * 8;
                float2 o = make_float2(acc[mt][n8][half * 2], acc[mt][n8][half * 2 + 1]);
                *(float2*)(y + (long long)r * H_DIM + col) = o;
            }
        }
    }
}

// ---------------------------------------------------------------------------
extern "C" void kernel_launch(void* const* d_in, const int* in_sizes, int n_in,
                              void* d_out, int out_size)
{
    const float* x  = (const float*)d_in[0];
    const float* wg = (const float*)d_in[1];
    const float* wu = (const float*)d_in[2];
    const float* wd = (const float*)d_in[3];
    float* y = (float*)d_out;

    cudaFuncSetAttribute(k_gateup, cudaFuncAttributeMaxDynamicSharedMemorySize, SMEM_BYTES);
    cudaFuncSetAttribute(k_down,   cudaFuncAttributeMaxDynamicSharedMemorySize, SMEM_BYTES);

    float *wgp, *wup, *wdp;
    cudaGetSymbolAddress((void**)&wgp, g_wgp);
    cudaGetSymbolAddress((void**)&wup, g_wup);
    cudaGetSymbolAddress((void**)&wdp, g_wdp);

    // converts into fragment-packed layouts
    k_cvt_xA<<<(int)(((long long)(M_DIM / 16) * (H_DIM / 8) * 32) / 256), 256>>>(x);
    k_cvt_wB<<<(int)(((long long)(I_DIM / 8) * (H_DIM / 8) * 32) / 256), 256>>>(wg, wgp, H_DIM, I_DIM);
    k_cvt_wB<<<(int)(((long long)(I_DIM / 8) * (H_DIM / 8) * 32) / 256), 256>>>(wu, wup, H_DIM, I_DIM);
    k_cvt_wB<<<(int)(((long long)(H_DIM / 8) * (I_DIM / 8) * 32) / 256), 256>>>(wd, wdp, I_DIM, H_DIM);

    const int grid1 = (M_DIM / 128) * (I_DIM / 64);    // 11008
    const int grid2 = (M_DIM / 128) * (H_DIM / 128);   // 2048
    k_gateup<<<grid1, 256, SMEM_BYTES>>>();
    k_down<<<grid2, 256, SMEM_BYTES>>>(y);
}